// round 15
// baseline (speedup 1.0000x reference)
#include <cuda_runtime.h>
#include <cuda_fp16.h>
#include <cuda_bf16.h>

// ---------------------------------------------------------------------------
// SAGE_SimWeighted: 3-layer GNN, cosine-sim softmax edge weights.
// N=50000, E=1.6M, DIN=DH=128, DOUT=64.
//
// fp16 storage for gathered/GEMM operands + self term R; fp32 accum.
// Tensor-core GEMMs (mma.m16n8k16). Dense CSR. Deferred softmax denom.
// Paired-edge MLP unroll in k_edge_csr (R13). Serial layer chain (R14).
// NEW: half-warp-per-edge aggregation — 2 independent 16-lane edge streams
// per warp (doubled gather MLP, halved serial FMA chains), combined via
// one shfl_xor(16) pass.
//
//   stream0: init -> cnt -> assign -> place -> [join s2] edge_csr
//            -> agg0 -> gemm1 -> agg1 -> gemm2 -> agg2
//   s2     : norm -> prepw_all -> gemm0          (overlapped with CSR build)
// ---------------------------------------------------------------------------

#define NMAX 50000
#define EMAX 1600000

__device__ __half g_xh  [(size_t)NMAX * 128];      // x cast fp16 (gemm0 input)
__device__ __half g_xnh [(size_t)NMAX * 128];      // normalized x, fp16
__device__ __half g_Hh  [(size_t)NMAX * 128];      // hidden, fp16
__device__ __half g_Ph  [(size_t)NMAX * 128];      // P (neighbor term), fp16
__device__ __half g_Rh  [(size_t)NMAX * 128];      // R (self term), fp16
__device__ __half g_W0t [256 * 128];               // [Wn0|Wr0]^T fp16
__device__ __half g_W1t [256 * 128];
__device__ __half g_W2t [128 * 128];
__device__ int    g_cnt [NMAX];
__device__ int    g_off [NMAX];                    // segment start per node
__device__ int    g_cur [NMAX];
__device__ float  g_inv [NMAX];                    // 1/(softmax denom)
__device__ int    g_total;
__device__ int2   g_csw [EMAX];                    // {src, raw_e bits}
__device__ int    g_is64;

// ---------------------------------------------------------------- mma wrapper
__device__ __forceinline__ void mma16816(float* c, const unsigned* a,
                                         unsigned b0, unsigned b1) {
    asm volatile(
        "mma.sync.aligned.m16n8k16.row.col.f32.f16.f16.f32 "
        "{%0,%1,%2,%3}, {%4,%5,%6,%7}, {%8,%9}, {%0,%1,%2,%3};"
        : "+f"(c[0]), "+f"(c[1]), "+f"(c[2]), "+f"(c[3])
        : "r"(a[0]), "r"(a[1]), "r"(a[2]), "r"(a[3]), "r"(b0), "r"(b1));
}

__device__ __forceinline__ int load_idx(const void* ei, long long pos) {
    if (g_is64) return (int)((const long long*)ei)[pos];
    return ((const int*)ei)[pos];
}

// ---------------------------------------------------------------- init+probe
__global__ void k_init(const void* ei, int e, int n) {
    int i = blockIdx.x * blockDim.x + threadIdx.x;
    int n4 = (n + 3) >> 2;
    if (i < n4) ((int4*)g_cnt)[i] = make_int4(0, 0, 0, 0);
    if (i == 0) g_total = 0;
    if (blockIdx.x == 0 && threadIdx.x < 32) {
        const long long* p = (const long long*)ei;
        int lim = e < 64 ? e : 64;
        bool bad = false;
        for (int j = threadIdx.x; j < lim; j += 32) {
            long long v = p[j];
            if (v < 0 || v >= (long long)n) bad = true;
        }
        unsigned m = __ballot_sync(0xffffffffu, bad);
        if (threadIdx.x == 0) g_is64 = m ? 0 : 1;
    }
}

// ---------------------------------------------------------------- norm + cast
__global__ void k_norm(const float* __restrict__ x, int n) {
    int w = (blockIdx.x * blockDim.x + threadIdx.x) >> 5;
    int lane = threadIdx.x & 31;
    if (w >= n) return;
    float4 a = ((const float4*)x)[(size_t)w * 32 + lane];
    float s = a.x * a.x + a.y * a.y + a.z * a.z + a.w * a.w;
    #pragma unroll
    for (int o = 16; o; o >>= 1) s += __shfl_xor_sync(0xffffffffu, s, o);
    float inv = 1.f / (sqrtf(s) + 1e-12f);

    half2 c0 = __floats2half2_rn(a.x, a.y);
    half2 c1 = __floats2half2_rn(a.z, a.w);
    uint2 qc; qc.x = *(unsigned*)&c0; qc.y = *(unsigned*)&c1;
    ((uint2*)g_xh)[(size_t)w * 32 + lane] = qc;

    half2 h0 = __floats2half2_rn(a.x * inv, a.y * inv);
    half2 h1 = __floats2half2_rn(a.z * inv, a.w * inv);
    uint2 qn; qn.x = *(unsigned*)&h0; qn.y = *(unsigned*)&h1;
    ((uint2*)g_xnh)[(size_t)w * 32 + lane] = qn;
}

// ---------------------------------------------------------------- weight prep
__global__ void k_prepw_all(const float* __restrict__ Wn0, const float* __restrict__ Wr0,
                            const float* __restrict__ Wn1, const float* __restrict__ Wr1,
                            const float* __restrict__ Wn2, const float* __restrict__ Wr2) {
    int i = blockIdx.x * blockDim.x + threadIdx.x;
    const int S01 = 256 * 128;
    const int S2  = 128 * 128;
    if (i < S01) {
        int j = i >> 7, k = i & 127;
        float v = (j < 128) ? Wn0[k * 128 + j] : Wr0[k * 128 + (j - 128)];
        g_W0t[j * 128 + k] = __float2half(v);
    } else if (i < 2 * S01) {
        int q = i - S01;
        int j = q >> 7, k = q & 127;
        float v = (j < 128) ? Wn1[k * 128 + j] : Wr1[k * 128 + (j - 128)];
        g_W1t[j * 128 + k] = __float2half(v);
    } else if (i < 2 * S01 + S2) {
        int q = i - 2 * S01;
        int j = q >> 7, k = q & 127;
        float v = (j < 64) ? Wn2[k * 64 + j] : Wr2[k * 64 + (j - 64)];
        g_W2t[j * 128 + k] = __float2half(v);
    }
}

// ---------------------------------------------------------------- degree cnt
__global__ void k_cnt(const void* __restrict__ ei, int e) {
    int i = blockIdx.x * blockDim.x + threadIdx.x;
    if (i >= e) return;
    int d = load_idx(ei, (long long)e + i);
    atomicAdd(&g_cnt[d], 1);
}

// ---------------------------------------------------------------- assign segs
__global__ void k_assign(int n) {
    int i = blockIdx.x * blockDim.x + threadIdx.x;
    int lane = threadIdx.x & 31;
    int v = (i < n) ? g_cnt[i] : 0;
    int x = v;
    #pragma unroll
    for (int o = 1; o < 32; o <<= 1) {
        int y = __shfl_up_sync(0xffffffffu, x, o);
        if (lane >= o) x += y;
    }
    int tot = __shfl_sync(0xffffffffu, x, 31);
    int base = 0;
    if (lane == 0) base = atomicAdd(&g_total, tot);
    base = __shfl_sync(0xffffffffu, base, 0);
    if (i < n) {
        int start = base + x - v;
        g_off[i] = start;
        g_cur[i] = start;
    }
}

// ---------------------------------------------------------------- place srcs
__global__ void k_place(const void* __restrict__ ei, int e) {
    int i = blockIdx.x * blockDim.x + threadIdx.x;
    if (i >= e) return;
    int s = load_idx(ei, i);
    int d = load_idx(ei, (long long)e + i);
    int pos = atomicAdd(&g_cur[d], 1);
    ((int*)g_csw)[2 * pos] = s;
}

// ---------------------------------------------------------------- edge weights
// warp per dst node; 4 groups of 8 lanes; 2 edges per group iteration.
__global__ void k_edge_csr(int n) {
    int w = (blockIdx.x * blockDim.x + threadIdx.x) >> 5;
    int lane = threadIdx.x & 31;
    if (w >= n) return;
    int g = lane >> 3, t = lane & 7;
    unsigned gmask = 0xFFu << (g * 8);
    int s0 = g_off[w];
    int nE = g_cnt[w];
    if (nE == 0) {
        if (lane == 0) g_inv[w] = 0.f;
        return;
    }

    float dreg[16];
    const uint4* dp = (const uint4*)(g_xnh + (size_t)w * 128);
    #pragma unroll
    for (int j = 0; j < 2; j++) {
        uint4 q = dp[t + j * 8];
        const half2* h = (const half2*)&q;
        #pragma unroll
        for (int c = 0; c < 4; c++) {
            float2 f = __half22float2(h[c]);
            dreg[j * 8 + c * 2 + 0] = f.x;
            dreg[j * 8 + c * 2 + 1] = f.y;
        }
    }

    float dsum = 0.f;
    int i = g;
    for (; i + 4 < nE; i += 8) {
        int posA = s0 + i, posB = s0 + i + 4;
        int sA = ((const int*)g_csw)[2 * posA];
        int sB = ((const int*)g_csw)[2 * posB];
        const uint4* spA = (const uint4*)(g_xnh + (size_t)sA * 128);
        const uint4* spB = (const uint4*)(g_xnh + (size_t)sB * 128);
        uint4 qa0 = spA[t], qa1 = spA[t + 8];
        uint4 qb0 = spB[t], qb1 = spB[t + 8];

        float dpA = 0.f, dpB = 0.f;
        {
            const half2* h0 = (const half2*)&qa0;
            const half2* h1 = (const half2*)&qa1;
            #pragma unroll
            for (int c = 0; c < 4; c++) {
                float2 f0 = __half22float2(h0[c]);
                float2 f1 = __half22float2(h1[c]);
                dpA += f0.x * dreg[c * 2] + f0.y * dreg[c * 2 + 1]
                     + f1.x * dreg[8 + c * 2] + f1.y * dreg[8 + c * 2 + 1];
            }
        }
        {
            const half2* h0 = (const half2*)&qb0;
            const half2* h1 = (const half2*)&qb1;
            #pragma unroll
            for (int c = 0; c < 4; c++) {
                float2 f0 = __half22float2(h0[c]);
                float2 f1 = __half22float2(h1[c]);
                dpB += f0.x * dreg[c * 2] + f0.y * dreg[c * 2 + 1]
                     + f1.x * dreg[8 + c * 2] + f1.y * dreg[8 + c * 2 + 1];
            }
        }
        dpA += __shfl_xor_sync(gmask, dpA, 4);
        dpB += __shfl_xor_sync(gmask, dpB, 4);
        dpA += __shfl_xor_sync(gmask, dpA, 2);
        dpB += __shfl_xor_sync(gmask, dpB, 2);
        dpA += __shfl_xor_sync(gmask, dpA, 1);
        dpB += __shfl_xor_sync(gmask, dpB, 1);
        if (t == 0) {
            float evA = __expf(dpA * 2.0f - 2.0f);   // /TAU(0.5), shift 2
            float evB = __expf(dpB * 2.0f - 2.0f);
            ((int*)g_csw)[2 * posA + 1] = __float_as_int(evA);
            ((int*)g_csw)[2 * posB + 1] = __float_as_int(evB);
            dsum += evA + evB;
        }
    }
    if (i < nE) {
        int pos = s0 + i;
        int sidx = ((const int*)g_csw)[2 * pos];
        const uint4* sp = (const uint4*)(g_xnh + (size_t)sidx * 128);
        uint4 q0 = sp[t], q1 = sp[t + 8];
        float dpacc = 0.f;
        const half2* h0 = (const half2*)&q0;
        const half2* h1 = (const half2*)&q1;
        #pragma unroll
        for (int c = 0; c < 4; c++) {
            float2 f0 = __half22float2(h0[c]);
            float2 f1 = __half22float2(h1[c]);
            dpacc += f0.x * dreg[c * 2] + f0.y * dreg[c * 2 + 1]
                   + f1.x * dreg[8 + c * 2] + f1.y * dreg[8 + c * 2 + 1];
        }
        dpacc += __shfl_xor_sync(gmask, dpacc, 4);
        dpacc += __shfl_xor_sync(gmask, dpacc, 2);
        dpacc += __shfl_xor_sync(gmask, dpacc, 1);
        if (t == 0) {
            float ev = __expf(dpacc * 2.0f - 2.0f);
            ((int*)g_csw)[2 * pos + 1] = __float_as_int(ev);
            dsum += ev;
        }
    }
    if (t != 0) dsum = 0.f;
    __syncwarp();
    dsum += __shfl_xor_sync(0xffffffffu, dsum, 8);
    dsum += __shfl_xor_sync(0xffffffffu, dsum, 16);
    if (lane == 0) g_inv[w] = 1.f / (dsum + 1e-16f);
}

// ---------------------------------------------------------------- tensor GEMM
#define SSTR 24
__global__ void __launch_bounds__(256)
k_hgemm(const __half* __restrict__ A, const __half* __restrict__ Bt,
        const float* __restrict__ cn, const float* __restrict__ cr,
        __half* __restrict__ Ph, __half* __restrict__ Rh,
        int n, int dout) {
    __shared__ __half As[2][128 * SSTR];
    __shared__ __half Bs[2][128 * SSTR];
    int tid = threadIdx.x;
    int m0 = blockIdx.x * 128, c0 = blockIdx.y * 128;

    int lr = tid >> 1, seg = tid & 1;
    bool aok = (m0 + lr) < n;
    const __half* Arow = A + (size_t)(m0 + lr) * 128 + seg * 8;
    const __half* Brow = Bt + (size_t)(c0 + lr) * 128 + seg * 8;
    int sidx = lr * SSTR + seg * 8;

    float acc[16][4];
    #pragma unroll
    for (int i = 0; i < 16; i++)
        #pragma unroll
        for (int q = 0; q < 4; q++) acc[i][q] = 0.f;

    uint4 aR = make_uint4(0, 0, 0, 0), bR;
    if (aok) aR = *(const uint4*)Arow;
    bR = *(const uint4*)Brow;
    *(uint4*)&As[0][sidx] = aR;
    *(uint4*)&Bs[0][sidx] = bR;
    __syncthreads();

    int wid = tid >> 5, lane = tid & 31;
    int wm = wid >> 1, wn = wid & 1;
    int qr = lane >> 2, qc = lane & 3;

    #pragma unroll
    for (int s = 0; s < 8; s++) {
        int cur = s & 1;
        if (s < 7) {
            aR = make_uint4(0, 0, 0, 0);
            if (aok) aR = *(const uint4*)(Arow + (s + 1) * 16);
            bR = *(const uint4*)(Brow + (s + 1) * 16);
        }
        unsigned afr[2][4];
        #pragma unroll
        for (int mi = 0; mi < 2; mi++) {
            const __half* base = &As[cur][(wm * 32 + mi * 16 + qr) * SSTR + qc * 2];
            afr[mi][0] = *(const unsigned*)(base);
            afr[mi][1] = *(const unsigned*)(base + 8 * SSTR);
            afr[mi][2] = *(const unsigned*)(base + 8);
            afr[mi][3] = *(const unsigned*)(base + 8 * SSTR + 8);
        }
        #pragma unroll
        for (int ni = 0; ni < 8; ni++) {
            const __half* bb = &Bs[cur][(wn * 64 + ni * 8 + qr) * SSTR + qc * 2];
            unsigned b0 = *(const unsigned*)bb;
            unsigned b1 = *(const unsigned*)(bb + 8);
            mma16816(acc[ni], afr[0], b0, b1);
            mma16816(acc[8 + ni], afr[1], b0, b1);
        }
        if (s < 7) {
            *(uint4*)&As[cur ^ 1][sidx] = aR;
            *(uint4*)&Bs[cur ^ 1][sidx] = bR;
            __syncthreads();
        }
    }

    #pragma unroll
    for (int mi = 0; mi < 2; mi++) {
        int rA = m0 + wm * 32 + mi * 16 + qr;
        int rB = rA + 8;
        #pragma unroll
        for (int ni = 0; ni < 8; ni++) {
            float* c = acc[mi * 8 + ni];
            int gc = c0 + wn * 64 + ni * 8 + qc * 2;
            if (gc < dout) {
                half2 hA = __floats2half2_rn(c[0], c[1]);
                half2 hB = __floats2half2_rn(c[2], c[3]);
                if (rA < n) *(half2*)(Ph + (size_t)rA * dout + gc) = hA;
                if (rB < n) *(half2*)(Ph + (size_t)rB * dout + gc) = hB;
            } else {
                int rc = gc - dout;
                float bx = cn[rc] + cr[rc];
                float by = cn[rc + 1] + cr[rc + 1];
                half2 hA = __floats2half2_rn(c[0] + bx, c[1] + by);
                half2 hB = __floats2half2_rn(c[2] + bx, c[3] + by);
                if (rA < n) *(half2*)(Rh + (size_t)rA * dout + rc) = hA;
                if (rB < n) *(half2*)(Rh + (size_t)rB * dout + rc) = hB;
            }
        }
    }
}

// ---------------------------------------------------------------- aggregate
// warp per node, 2 half-warp edge streams: group h (lane>>4) processes edge
// slots h, h+2, ... of each 32-descriptor chunk; 16 lanes gather a full Ph
// row per edge (uint4 for DO=128, uint2 for DO=64). Groups combine via
// shfl_xor(16); lanes 0..15 run the epilogue.
template <int DO, bool DOBN, bool HOUT>
__global__ void k_agg(const __half* __restrict__ Ph, const __half* __restrict__ Rh,
                      const float* __restrict__ gg, const float* __restrict__ bb,
                      const float* __restrict__ mm, const float* __restrict__ vv,
                      void* __restrict__ outv, int n) {
    int w = (blockIdx.x * blockDim.x + threadIdx.x) >> 5;
    int lane = threadIdx.x & 31;
    if (w >= n) return;
    int h = lane >> 4, t = lane & 15;
    unsigned gmask = 0xFFFFu << (h * 16);
    constexpr int V = DO / 16;          // 8 for DO=128, 4 for DO=64
    float acc[V];
    #pragma unroll
    for (int c = 0; c < V; c++) acc[c] = 0.f;

    int s0 = g_off[w];
    int nE = g_cnt[w];

    for (int base = 0; base < nE; base += 32) {
        int m = min(32, nE - base);
        // lane (h*16 + t) holds descriptor for edge slot (h + 2t) of chunk
        int myidx = h + 2 * t;
        int2 v = make_int2(0, 0);
        if (myidx < m) v = __ldg(&g_csw[s0 + base + myidx]);
        int cg = (m - h + 1) >> 1;      // group h handles cg edges
        for (int j = 0; j < cg; j++) {
            int src = __shfl_sync(gmask, v.x, h * 16 + j);
            float w2 = __int_as_float(__shfl_sync(gmask, v.y, h * 16 + j));
            if constexpr (DO == 128) {
                uint4 q = ((const uint4*)(Ph + (size_t)src * DO))[t];
                const half2* hh = (const half2*)&q;
                #pragma unroll
                for (int c = 0; c < 4; c++) {
                    float2 f = __half22float2(hh[c]);
                    acc[c * 2 + 0] += w2 * f.x;
                    acc[c * 2 + 1] += w2 * f.y;
                }
            } else {
                uint2 q = ((const uint2*)(Ph + (size_t)src * DO))[t];
                const half2* hh = (const half2*)&q;
                #pragma unroll
                for (int c = 0; c < 2; c++) {
                    float2 f = __half22float2(hh[c]);
                    acc[c * 2 + 0] += w2 * f.x;
                    acc[c * 2 + 1] += w2 * f.y;
                }
            }
        }
    }

    // combine the two half-warp streams (full-warp convergent point)
    #pragma unroll
    for (int c = 0; c < V; c++)
        acc[c] += __shfl_xor_sync(0xffffffffu, acc[c], 16);

    if (h != 0) return;                 // lanes 0..15 do the epilogue
    float inv = g_inv[w];

    float r[V];
    if constexpr (DO == 128) {
        uint4 q = ((const uint4*)(Rh + (size_t)w * DO))[t];
        const half2* hh = (const half2*)&q;
        #pragma unroll
        for (int c = 0; c < 4; c++) {
            float2 f = __half22float2(hh[c]);
            r[c * 2 + 0] = f.x; r[c * 2 + 1] = f.y;
        }
    } else {
        uint2 q = ((const uint2*)(Rh + (size_t)w * DO))[t];
        const half2* hh = (const half2*)&q;
        #pragma unroll
        for (int c = 0; c < 2; c++) {
            float2 f = __half22float2(hh[c]);
            r[c * 2 + 0] = f.x; r[c * 2 + 1] = f.y;
        }
    }

    float hres[V];
    #pragma unroll
    for (int c = 0; c < V; c++) {
        int d = t * V + c;
        float hv = acc[c] * inv + r[c];
        if (DOBN) {
            float sc = gg[d] * rsqrtf(vv[d] + 1e-5f);
            hv = (hv - mm[d]) * sc + bb[d];
            hv = fmaxf(hv, 0.f);
        }
        hres[c] = hv;
    }
    if constexpr (HOUT) {
        __half* out = (__half*)outv;
        if constexpr (DO == 128) {
            half2 h0 = __floats2half2_rn(hres[0], hres[1]);
            half2 h1 = __floats2half2_rn(hres[2], hres[3]);
            half2 h2 = __floats2half2_rn(hres[4], hres[5]);
            half2 h3 = __floats2half2_rn(hres[6], hres[7]);
            uint4 q;
            q.x = *(unsigned*)&h0; q.y = *(unsigned*)&h1;
            q.z = *(unsigned*)&h2; q.w = *(unsigned*)&h3;
            ((uint4*)(out + (size_t)w * DO))[t] = q;
        } else {
            half2 h0 = __floats2half2_rn(hres[0], hres[1]);
            half2 h1 = __floats2half2_rn(hres[2], hres[3]);
            uint2 q; q.x = *(unsigned*)&h0; q.y = *(unsigned*)&h1;
            ((uint2*)(out + (size_t)w * DO))[t] = q;
        }
    } else {
        float* out = (float*)outv;
        if constexpr (DO == 128) {
            ((float4*)(out + (size_t)w * DO))[t * 2 + 0] =
                make_float4(hres[0], hres[1], hres[2], hres[3]);
            ((float4*)(out + (size_t)w * DO))[t * 2 + 1] =
                make_float4(hres[4], hres[5], hres[6], hres[7]);
        } else {
            ((float4*)(out + (size_t)w * DO))[t] =
                make_float4(hres[0], hres[1], hres[2], hres[3]);
        }
    }
}

// ---------------------------------------------------------------- launch
extern "C" void kernel_launch(void* const* d_in, const int* in_sizes, int n_in,
                              void* d_out, int out_size) {
    const float* x   = (const float*)d_in[0];
    const void*  ei  = d_in[1];
    const float* Wn0 = (const float*)d_in[2];
    const float* cn0 = (const float*)d_in[3];
    const float* Wr0 = (const float*)d_in[4];
    const float* cr0 = (const float*)d_in[5];
    const float* Wn1 = (const float*)d_in[6];
    const float* cn1 = (const float*)d_in[7];
    const float* Wr1 = (const float*)d_in[8];
    const float* cr1 = (const float*)d_in[9];
    const float* Wn2 = (const float*)d_in[10];
    const float* cn2 = (const float*)d_in[11];
    const float* Wr2 = (const float*)d_in[12];
    const float* cr2 = (const float*)d_in[13];
    const float* g0  = (const float*)d_in[14];
    const float* b0  = (const float*)d_in[15];
    const float* m0  = (const float*)d_in[16];
    const float* v0  = (const float*)d_in[17];
    const float* g1  = (const float*)d_in[18];
    const float* b1  = (const float*)d_in[19];
    const float* m1  = (const float*)d_in[20];
    const float* v1  = (const float*)d_in[21];

    int n = in_sizes[0] / 128;
    int e = in_sizes[1] / 2;
    float* out = (float*)d_out;

    __half *xh, *Hh, *Ph, *Rh, *W0t, *W1t, *W2t;
    cudaGetSymbolAddress((void**)&xh, g_xh);
    cudaGetSymbolAddress((void**)&Hh, g_Hh);
    cudaGetSymbolAddress((void**)&Ph, g_Ph);
    cudaGetSymbolAddress((void**)&Rh, g_Rh);
    cudaGetSymbolAddress((void**)&W0t, g_W0t);
    cudaGetSymbolAddress((void**)&W1t, g_W1t);
    cudaGetSymbolAddress((void**)&W2t, g_W2t);

    static cudaStream_t s2 = nullptr;
    static cudaEvent_t ev0 = nullptr, ev1 = nullptr;
    if (!s2) {
        cudaStreamCreateWithFlags(&s2, cudaStreamNonBlocking);
        cudaEventCreateWithFlags(&ev0, cudaEventDisableTiming);
        cudaEventCreateWithFlags(&ev1, cudaEventDisableTiming);
    }

    int gx = (n + 127) / 128;
    const int PWTOT = 2 * 256 * 128 + 128 * 128;

    // s2: norm -> weight prep -> gemm0, overlapped with CSR build
    cudaEventRecord(ev0, 0);
    cudaStreamWaitEvent(s2, ev0, 0);
    k_norm<<<(n + 7) / 8, 256, 0, s2>>>(x, n);
    k_prepw_all<<<(PWTOT + 255) / 256, 256, 0, s2>>>(Wn0, Wr0, Wn1, Wr1, Wn2, Wr2);
    k_hgemm<<<dim3(gx, 2), 256, 0, s2>>>(xh, W0t, cn0, cr0, Ph, Rh, n, 128);
    cudaEventRecord(ev1, s2);

    // stream0: dense CSR build
    k_init<<<(n + 255) / 256, 256>>>(ei, e, n);
    k_cnt<<<(e + 255) / 256, 256>>>(ei, e);
    k_assign<<<(n + 255) / 256, 256>>>(n);
    k_place<<<(e + 255) / 256, 256>>>(ei, e);

    // join gemm0, then serial layer chain
    cudaStreamWaitEvent(0, ev1, 0);
    k_edge_csr<<<(n + 7) / 8, 256>>>(n);
    k_agg<128, true, true><<<(n + 7) / 8, 256>>>(Ph, Rh, g0, b0, m0, v0, Hh, n);
    k_hgemm<<<dim3(gx, 2), 256>>>(Hh, W1t, cn1, cr1, Ph, Rh, n, 128);
    k_agg<128, true, true><<<(n + 7) / 8, 256>>>(Ph, Rh, g1, b1, m1, v1, Hh, n);
    k_hgemm<<<dim3(gx, 1), 256>>>(Hh, W2t, cn2, cr2, Ph, Rh, n, 64);
    k_agg<64, false, false><<<(n + 7) / 8, 256>>>(Ph, Rh, g0, b0, m0, v0, out, n);
}

// round 16
// speedup vs baseline: 1.1096x; 1.1096x over previous
#include <cuda_runtime.h>
#include <cuda_fp16.h>
#include <cuda_bf16.h>

// ---------------------------------------------------------------------------
// SAGE_SimWeighted: 3-layer GNN, cosine-sim softmax edge weights.
// N=50000, E=1.6M, DIN=DH=128, DOUT=64.   FINAL (locked R14 configuration).
//
// fp16 storage for gathered/GEMM operands + self term R; fp32 accum.
// Tensor-core GEMMs (mma.m16n8k16). Dense CSR. Deferred softmax denom.
// Paired-edge MLP unroll in k_edge_csr. Serial layer chain.
//
//   stream0: init -> cnt -> assign -> place -> [join s2] edge_csr
//            -> agg0 -> gemm1 -> agg1 -> gemm2 -> agg2
//   s2     : norm -> prepw_all -> gemm0          (overlapped with CSR build)
// ---------------------------------------------------------------------------

#define NMAX 50000
#define EMAX 1600000

__device__ __half g_xh  [(size_t)NMAX * 128];      // x cast fp16 (gemm0 input)
__device__ __half g_xnh [(size_t)NMAX * 128];      // normalized x, fp16
__device__ __half g_Hh  [(size_t)NMAX * 128];      // hidden, fp16
__device__ __half g_Ph  [(size_t)NMAX * 128];      // P (neighbor term), fp16
__device__ __half g_Rh  [(size_t)NMAX * 128];      // R (self term), fp16
__device__ __half g_W0t [256 * 128];               // [Wn0|Wr0]^T fp16
__device__ __half g_W1t [256 * 128];
__device__ __half g_W2t [128 * 128];
__device__ int    g_cnt [NMAX];
__device__ int    g_off [NMAX];                    // segment start per node
__device__ int    g_cur [NMAX];
__device__ float  g_inv [NMAX];                    // 1/(softmax denom)
__device__ int    g_total;
__device__ int2   g_csw [EMAX];                    // {src, raw_e bits}
__device__ int    g_is64;

// ---------------------------------------------------------------- mma wrapper
__device__ __forceinline__ void mma16816(float* c, const unsigned* a,
                                         unsigned b0, unsigned b1) {
    asm volatile(
        "mma.sync.aligned.m16n8k16.row.col.f32.f16.f16.f32 "
        "{%0,%1,%2,%3}, {%4,%5,%6,%7}, {%8,%9}, {%0,%1,%2,%3};"
        : "+f"(c[0]), "+f"(c[1]), "+f"(c[2]), "+f"(c[3])
        : "r"(a[0]), "r"(a[1]), "r"(a[2]), "r"(a[3]), "r"(b0), "r"(b1));
}

__device__ __forceinline__ int load_idx(const void* ei, long long pos) {
    if (g_is64) return (int)((const long long*)ei)[pos];
    return ((const int*)ei)[pos];
}

// ---------------------------------------------------------------- init+probe
__global__ void k_init(const void* ei, int e, int n) {
    int i = blockIdx.x * blockDim.x + threadIdx.x;
    int n4 = (n + 3) >> 2;
    if (i < n4) ((int4*)g_cnt)[i] = make_int4(0, 0, 0, 0);
    if (i == 0) g_total = 0;
    if (blockIdx.x == 0 && threadIdx.x < 32) {
        const long long* p = (const long long*)ei;
        int lim = e < 64 ? e : 64;
        bool bad = false;
        for (int j = threadIdx.x; j < lim; j += 32) {
            long long v = p[j];
            if (v < 0 || v >= (long long)n) bad = true;
        }
        unsigned m = __ballot_sync(0xffffffffu, bad);
        if (threadIdx.x == 0) g_is64 = m ? 0 : 1;
    }
}

// ---------------------------------------------------------------- norm + cast
__global__ void k_norm(const float* __restrict__ x, int n) {
    int w = (blockIdx.x * blockDim.x + threadIdx.x) >> 5;
    int lane = threadIdx.x & 31;
    if (w >= n) return;
    float4 a = ((const float4*)x)[(size_t)w * 32 + lane];
    float s = a.x * a.x + a.y * a.y + a.z * a.z + a.w * a.w;
    #pragma unroll
    for (int o = 16; o; o >>= 1) s += __shfl_xor_sync(0xffffffffu, s, o);
    float inv = 1.f / (sqrtf(s) + 1e-12f);

    half2 c0 = __floats2half2_rn(a.x, a.y);
    half2 c1 = __floats2half2_rn(a.z, a.w);
    uint2 qc; qc.x = *(unsigned*)&c0; qc.y = *(unsigned*)&c1;
    ((uint2*)g_xh)[(size_t)w * 32 + lane] = qc;

    half2 h0 = __floats2half2_rn(a.x * inv, a.y * inv);
    half2 h1 = __floats2half2_rn(a.z * inv, a.w * inv);
    uint2 qn; qn.x = *(unsigned*)&h0; qn.y = *(unsigned*)&h1;
    ((uint2*)g_xnh)[(size_t)w * 32 + lane] = qn;
}

// ---------------------------------------------------------------- weight prep
__global__ void k_prepw_all(const float* __restrict__ Wn0, const float* __restrict__ Wr0,
                            const float* __restrict__ Wn1, const float* __restrict__ Wr1,
                            const float* __restrict__ Wn2, const float* __restrict__ Wr2) {
    int i = blockIdx.x * blockDim.x + threadIdx.x;
    const int S01 = 256 * 128;
    const int S2  = 128 * 128;
    if (i < S01) {
        int j = i >> 7, k = i & 127;
        float v = (j < 128) ? Wn0[k * 128 + j] : Wr0[k * 128 + (j - 128)];
        g_W0t[j * 128 + k] = __float2half(v);
    } else if (i < 2 * S01) {
        int q = i - S01;
        int j = q >> 7, k = q & 127;
        float v = (j < 128) ? Wn1[k * 128 + j] : Wr1[k * 128 + (j - 128)];
        g_W1t[j * 128 + k] = __float2half(v);
    } else if (i < 2 * S01 + S2) {
        int q = i - 2 * S01;
        int j = q >> 7, k = q & 127;
        float v = (j < 64) ? Wn2[k * 64 + j] : Wr2[k * 64 + (j - 64)];
        g_W2t[j * 128 + k] = __float2half(v);
    }
}

// ---------------------------------------------------------------- degree cnt
__global__ void k_cnt(const void* __restrict__ ei, int e) {
    int i = blockIdx.x * blockDim.x + threadIdx.x;
    if (i >= e) return;
    int d = load_idx(ei, (long long)e + i);
    atomicAdd(&g_cnt[d], 1);
}

// ---------------------------------------------------------------- assign segs
__global__ void k_assign(int n) {
    int i = blockIdx.x * blockDim.x + threadIdx.x;
    int lane = threadIdx.x & 31;
    int v = (i < n) ? g_cnt[i] : 0;
    int x = v;
    #pragma unroll
    for (int o = 1; o < 32; o <<= 1) {
        int y = __shfl_up_sync(0xffffffffu, x, o);
        if (lane >= o) x += y;
    }
    int tot = __shfl_sync(0xffffffffu, x, 31);
    int base = 0;
    if (lane == 0) base = atomicAdd(&g_total, tot);
    base = __shfl_sync(0xffffffffu, base, 0);
    if (i < n) {
        int start = base + x - v;
        g_off[i] = start;
        g_cur[i] = start;
    }
}

// ---------------------------------------------------------------- place srcs
__global__ void k_place(const void* __restrict__ ei, int e) {
    int i = blockIdx.x * blockDim.x + threadIdx.x;
    if (i >= e) return;
    int s = load_idx(ei, i);
    int d = load_idx(ei, (long long)e + i);
    int pos = atomicAdd(&g_cur[d], 1);
    ((int*)g_csw)[2 * pos] = s;
}

// ---------------------------------------------------------------- edge weights
// warp per dst node; 4 groups of 8 lanes; 2 edges per group iteration
// (i, i+4): doubled gather MLP, interleaved reduction chains.
__global__ void k_edge_csr(int n) {
    int w = (blockIdx.x * blockDim.x + threadIdx.x) >> 5;
    int lane = threadIdx.x & 31;
    if (w >= n) return;
    int g = lane >> 3, t = lane & 7;
    unsigned gmask = 0xFFu << (g * 8);
    int s0 = g_off[w];
    int nE = g_cnt[w];
    if (nE == 0) {
        if (lane == 0) g_inv[w] = 0.f;
        return;
    }

    float dreg[16];
    const uint4* dp = (const uint4*)(g_xnh + (size_t)w * 128);
    #pragma unroll
    for (int j = 0; j < 2; j++) {
        uint4 q = dp[t + j * 8];
        const half2* h = (const half2*)&q;
        #pragma unroll
        for (int c = 0; c < 4; c++) {
            float2 f = __half22float2(h[c]);
            dreg[j * 8 + c * 2 + 0] = f.x;
            dreg[j * 8 + c * 2 + 1] = f.y;
        }
    }

    float dsum = 0.f;
    int i = g;
    for (; i + 4 < nE; i += 8) {
        int posA = s0 + i, posB = s0 + i + 4;
        int sA = ((const int*)g_csw)[2 * posA];
        int sB = ((const int*)g_csw)[2 * posB];
        const uint4* spA = (const uint4*)(g_xnh + (size_t)sA * 128);
        const uint4* spB = (const uint4*)(g_xnh + (size_t)sB * 128);
        uint4 qa0 = spA[t], qa1 = spA[t + 8];
        uint4 qb0 = spB[t], qb1 = spB[t + 8];

        float dpA = 0.f, dpB = 0.f;
        {
            const half2* h0 = (const half2*)&qa0;
            const half2* h1 = (const half2*)&qa1;
            #pragma unroll
            for (int c = 0; c < 4; c++) {
                float2 f0 = __half22float2(h0[c]);
                float2 f1 = __half22float2(h1[c]);
                dpA += f0.x * dreg[c * 2] + f0.y * dreg[c * 2 + 1]
                     + f1.x * dreg[8 + c * 2] + f1.y * dreg[8 + c * 2 + 1];
            }
        }
        {
            const half2* h0 = (const half2*)&qb0;
            const half2* h1 = (const half2*)&qb1;
            #pragma unroll
            for (int c = 0; c < 4; c++) {
                float2 f0 = __half22float2(h0[c]);
                float2 f1 = __half22float2(h1[c]);
                dpB += f0.x * dreg[c * 2] + f0.y * dreg[c * 2 + 1]
                     + f1.x * dreg[8 + c * 2] + f1.y * dreg[8 + c * 2 + 1];
            }
        }
        dpA += __shfl_xor_sync(gmask, dpA, 4);
        dpB += __shfl_xor_sync(gmask, dpB, 4);
        dpA += __shfl_xor_sync(gmask, dpA, 2);
        dpB += __shfl_xor_sync(gmask, dpB, 2);
        dpA += __shfl_xor_sync(gmask, dpA, 1);
        dpB += __shfl_xor_sync(gmask, dpB, 1);
        if (t == 0) {
            float evA = __expf(dpA * 2.0f - 2.0f);   // /TAU(0.5), shift 2
            float evB = __expf(dpB * 2.0f - 2.0f);
            ((int*)g_csw)[2 * posA + 1] = __float_as_int(evA);
            ((int*)g_csw)[2 * posB + 1] = __float_as_int(evB);
            dsum += evA + evB;
        }
    }
    if (i < nE) {
        int pos = s0 + i;
        int sidx = ((const int*)g_csw)[2 * pos];
        const uint4* sp = (const uint4*)(g_xnh + (size_t)sidx * 128);
        uint4 q0 = sp[t], q1 = sp[t + 8];
        float dpacc = 0.f;
        const half2* h0 = (const half2*)&q0;
        const half2* h1 = (const half2*)&q1;
        #pragma unroll
        for (int c = 0; c < 4; c++) {
            float2 f0 = __half22float2(h0[c]);
            float2 f1 = __half22float2(h1[c]);
            dpacc += f0.x * dreg[c * 2] + f0.y * dreg[c * 2 + 1]
                   + f1.x * dreg[8 + c * 2] + f1.y * dreg[8 + c * 2 + 1];
        }
        dpacc += __shfl_xor_sync(gmask, dpacc, 4);
        dpacc += __shfl_xor_sync(gmask, dpacc, 2);
        dpacc += __shfl_xor_sync(gmask, dpacc, 1);
        if (t == 0) {
            float ev = __expf(dpacc * 2.0f - 2.0f);
            ((int*)g_csw)[2 * pos + 1] = __float_as_int(ev);
            dsum += ev;
        }
    }
    if (t != 0) dsum = 0.f;
    __syncwarp();
    dsum += __shfl_xor_sync(0xffffffffu, dsum, 8);
    dsum += __shfl_xor_sync(0xffffffffu, dsum, 16);
    if (lane == 0) g_inv[w] = 1.f / (dsum + 1e-16f);
}

// ---------------------------------------------------------------- tensor GEMM
#define SSTR 24
__global__ void __launch_bounds__(256)
k_hgemm(const __half* __restrict__ A, const __half* __restrict__ Bt,
        const float* __restrict__ cn, const float* __restrict__ cr,
        __half* __restrict__ Ph, __half* __restrict__ Rh,
        int n, int dout) {
    __shared__ __half As[2][128 * SSTR];
    __shared__ __half Bs[2][128 * SSTR];
    int tid = threadIdx.x;
    int m0 = blockIdx.x * 128, c0 = blockIdx.y * 128;

    int lr = tid >> 1, seg = tid & 1;
    bool aok = (m0 + lr) < n;
    const __half* Arow = A + (size_t)(m0 + lr) * 128 + seg * 8;
    const __half* Brow = Bt + (size_t)(c0 + lr) * 128 + seg * 8;
    int sidx = lr * SSTR + seg * 8;

    float acc[16][4];
    #pragma unroll
    for (int i = 0; i < 16; i++)
        #pragma unroll
        for (int q = 0; q < 4; q++) acc[i][q] = 0.f;

    uint4 aR = make_uint4(0, 0, 0, 0), bR;
    if (aok) aR = *(const uint4*)Arow;
    bR = *(const uint4*)Brow;
    *(uint4*)&As[0][sidx] = aR;
    *(uint4*)&Bs[0][sidx] = bR;
    __syncthreads();

    int wid = tid >> 5, lane = tid & 31;
    int wm = wid >> 1, wn = wid & 1;
    int qr = lane >> 2, qc = lane & 3;

    #pragma unroll
    for (int s = 0; s < 8; s++) {
        int cur = s & 1;
        if (s < 7) {
            aR = make_uint4(0, 0, 0, 0);
            if (aok) aR = *(const uint4*)(Arow + (s + 1) * 16);
            bR = *(const uint4*)(Brow + (s + 1) * 16);
        }
        unsigned afr[2][4];
        #pragma unroll
        for (int mi = 0; mi < 2; mi++) {
            const __half* base = &As[cur][(wm * 32 + mi * 16 + qr) * SSTR + qc * 2];
            afr[mi][0] = *(const unsigned*)(base);
            afr[mi][1] = *(const unsigned*)(base + 8 * SSTR);
            afr[mi][2] = *(const unsigned*)(base + 8);
            afr[mi][3] = *(const unsigned*)(base + 8 * SSTR + 8);
        }
        #pragma unroll
        for (int ni = 0; ni < 8; ni++) {
            const __half* bb = &Bs[cur][(wn * 64 + ni * 8 + qr) * SSTR + qc * 2];
            unsigned b0 = *(const unsigned*)bb;
            unsigned b1 = *(const unsigned*)(bb + 8);
            mma16816(acc[ni], afr[0], b0, b1);
            mma16816(acc[8 + ni], afr[1], b0, b1);
        }
        if (s < 7) {
            *(uint4*)&As[cur ^ 1][sidx] = aR;
            *(uint4*)&Bs[cur ^ 1][sidx] = bR;
            __syncthreads();
        }
    }

    #pragma unroll
    for (int mi = 0; mi < 2; mi++) {
        int rA = m0 + wm * 32 + mi * 16 + qr;
        int rB = rA + 8;
        #pragma unroll
        for (int ni = 0; ni < 8; ni++) {
            float* c = acc[mi * 8 + ni];
            int gc = c0 + wn * 64 + ni * 8 + qc * 2;
            if (gc < dout) {
                half2 hA = __floats2half2_rn(c[0], c[1]);
                half2 hB = __floats2half2_rn(c[2], c[3]);
                if (rA < n) *(half2*)(Ph + (size_t)rA * dout + gc) = hA;
                if (rB < n) *(half2*)(Ph + (size_t)rB * dout + gc) = hB;
            } else {
                int rc = gc - dout;
                float bx = cn[rc] + cr[rc];
                float by = cn[rc + 1] + cr[rc + 1];
                half2 hA = __floats2half2_rn(c[0] + bx, c[1] + by);
                half2 hB = __floats2half2_rn(c[2] + bx, c[3] + by);
                if (rA < n) *(half2*)(Rh + (size_t)rA * dout + rc) = hA;
                if (rB < n) *(half2*)(Rh + (size_t)rB * dout + rc) = hB;
            }
        }
    }
}

// ---------------------------------------------------------------- aggregate
// warp per node; descriptor loads batched 8-deep.
template <int DO, bool DOBN, bool HOUT>
__global__ void k_agg(const __half* __restrict__ Ph, const __half* __restrict__ Rh,
                      const float* __restrict__ gg, const float* __restrict__ bb,
                      const float* __restrict__ mm, const float* __restrict__ vv,
                      void* __restrict__ outv, int n) {
    int w = (blockIdx.x * blockDim.x + threadIdx.x) >> 5;
    int lane = threadIdx.x & 31;
    if (w >= n) return;
    constexpr int V = DO / 32;
    float acc[V];
    #pragma unroll
    for (int c = 0; c < V; c++) acc[c] = 0.f;

    int s = g_off[w];
    int e2 = s + g_cnt[w];

    auto body = [&](int2 v) {
        float w2 = __int_as_float(v.y);
        const __half* prow = Ph + (size_t)v.x * DO;
        if constexpr (V == 4) {
            uint2 q = ((const uint2*)prow)[lane];
            float2 p01 = __half22float2(*(const half2*)&q.x);
            float2 p23 = __half22float2(*(const half2*)&q.y);
            acc[0] += w2 * p01.x; acc[1] += w2 * p01.y;
            acc[2] += w2 * p23.x; acc[3] += w2 * p23.y;
        } else {
            unsigned q = ((const unsigned*)prow)[lane];
            float2 p = __half22float2(*(const half2*)&q);
            acc[0] += w2 * p.x; acc[1] += w2 * p.y;
        }
    };

    int idx = s;
    for (; idx + 8 <= e2; idx += 8) {
        int2 v[8];
        #pragma unroll
        for (int u = 0; u < 8; u++) v[u] = __ldg(&g_csw[idx + u]);
        #pragma unroll
        for (int u = 0; u < 8; u++) body(v[u]);
    }
    for (; idx + 4 <= e2; idx += 4) {
        int2 v[4];
        #pragma unroll
        for (int u = 0; u < 4; u++) v[u] = __ldg(&g_csw[idx + u]);
        #pragma unroll
        for (int u = 0; u < 4; u++) body(v[u]);
    }
    for (; idx < e2; idx++) body(__ldg(&g_csw[idx]));

    float inv = g_inv[w];

    float r[V];
    const __half* rrow = Rh + (size_t)w * DO;
    if constexpr (V == 4) {
        uint2 q = ((const uint2*)rrow)[lane];
        float2 r01 = __half22float2(*(const half2*)&q.x);
        float2 r23 = __half22float2(*(const half2*)&q.y);
        r[0] = r01.x; r[1] = r01.y; r[2] = r23.x; r[3] = r23.y;
    } else {
        unsigned q = ((const unsigned*)rrow)[lane];
        float2 rv = __half22float2(*(const half2*)&q);
        r[0] = rv.x; r[1] = rv.y;
    }

    float h[V];
    #pragma unroll
    for (int c = 0; c < V; c++) {
        int d = lane * V + c;
        float hv = acc[c] * inv + r[c];
        if (DOBN) {
            float sc = gg[d] * rsqrtf(vv[d] + 1e-5f);
            hv = (hv - mm[d]) * sc + bb[d];
            hv = fmaxf(hv, 0.f);
        }
        h[c] = hv;
    }
    if constexpr (HOUT) {
        __half* out = (__half*)outv;
        if constexpr (V == 4) {
            half2 h0 = __floats2half2_rn(h[0], h[1]);
            half2 h1 = __floats2half2_rn(h[2], h[3]);
            uint2 q; q.x = *(unsigned*)&h0; q.y = *(unsigned*)&h1;
            ((uint2*)(out + (size_t)w * DO))[lane] = q;
        } else {
            half2 h0 = __floats2half2_rn(h[0], h[1]);
            ((unsigned*)(out + (size_t)w * DO))[lane] = *(unsigned*)&h0;
        }
    } else {
        float* out = (float*)outv;
        if constexpr (V == 4) {
            ((float4*)(out + (size_t)w * DO))[lane] =
                make_float4(h[0], h[1], h[2], h[3]);
        } else {
            ((float2*)(out + (size_t)w * DO))[lane] = make_float2(h[0], h[1]);
        }
    }
}

// ---------------------------------------------------------------- launch
extern "C" void kernel_launch(void* const* d_in, const int* in_sizes, int n_in,
                              void* d_out, int out_size) {
    const float* x   = (const float*)d_in[0];
    const void*  ei  = d_in[1];
    const float* Wn0 = (const float*)d_in[2];
    const float* cn0 = (const float*)d_in[3];
    const float* Wr0 = (const float*)d_in[4];
    const float* cr0 = (const float*)d_in[5];
    const float* Wn1 = (const float*)d_in[6];
    const float* cn1 = (const float*)d_in[7];
    const float* Wr1 = (const float*)d_in[8];
    const float* cr1 = (const float*)d_in[9];
    const float* Wn2 = (const float*)d_in[10];
    const float* cn2 = (const float*)d_in[11];
    const float* Wr2 = (const float*)d_in[12];
    const float* cr2 = (const float*)d_in[13];
    const float* g0  = (const float*)d_in[14];
    const float* b0  = (const float*)d_in[15];
    const float* m0  = (const float*)d_in[16];
    const float* v0  = (const float*)d_in[17];
    const float* g1  = (const float*)d_in[18];
    const float* b1  = (const float*)d_in[19];
    const float* m1  = (const float*)d_in[20];
    const float* v1  = (const float*)d_in[21];

    int n = in_sizes[0] / 128;
    int e = in_sizes[1] / 2;
    float* out = (float*)d_out;

    __half *xh, *Hh, *Ph, *Rh, *W0t, *W1t, *W2t;
    cudaGetSymbolAddress((void**)&xh, g_xh);
    cudaGetSymbolAddress((void**)&Hh, g_Hh);
    cudaGetSymbolAddress((void**)&Ph, g_Ph);
    cudaGetSymbolAddress((void**)&Rh, g_Rh);
    cudaGetSymbolAddress((void**)&W0t, g_W0t);
    cudaGetSymbolAddress((void**)&W1t, g_W1t);
    cudaGetSymbolAddress((void**)&W2t, g_W2t);

    static cudaStream_t s2 = nullptr;
    static cudaEvent_t ev0 = nullptr, ev1 = nullptr;
    if (!s2) {
        cudaStreamCreateWithFlags(&s2, cudaStreamNonBlocking);
        cudaEventCreateWithFlags(&ev0, cudaEventDisableTiming);
        cudaEventCreateWithFlags(&ev1, cudaEventDisableTiming);
    }

    int gx = (n + 127) / 128;
    const int PWTOT = 2 * 256 * 128 + 128 * 128;

    // s2: norm -> weight prep -> gemm0, overlapped with CSR build
    cudaEventRecord(ev0, 0);
    cudaStreamWaitEvent(s2, ev0, 0);
    k_norm<<<(n + 7) / 8, 256, 0, s2>>>(x, n);
    k_prepw_all<<<(PWTOT + 255) / 256, 256, 0, s2>>>(Wn0, Wr0, Wn1, Wr1, Wn2, Wr2);
    k_hgemm<<<dim3(gx, 2), 256, 0, s2>>>(xh, W0t, cn0, cr0, Ph, Rh, n, 128);
    cudaEventRecord(ev1, s2);

    // stream0: dense CSR build
    k_init<<<(n + 255) / 256, 256>>>(ei, e, n);
    k_cnt<<<(e + 255) / 256, 256>>>(ei, e);
    k_assign<<<(n + 255) / 256, 256>>>(n);
    k_place<<<(e + 255) / 256, 256>>>(ei, e);

    // join gemm0, then serial layer chain
    cudaStreamWaitEvent(0, ev1, 0);
    k_edge_csr<<<(n + 7) / 8, 256>>>(n);
    k_agg<128, true, true><<<(n + 7) / 8, 256>>>(Ph, Rh, g0, b0, m0, v0, Hh, n);
    k_hgemm<<<dim3(gx, 2), 256>>>(Hh, W1t, cn1, cr1, Ph, Rh, n, 128);
    k_agg<128, true, true><<<(n + 7) / 8, 256>>>(Ph, Rh, g1, b1, m1, v1, Hh, n);
    k_hgemm<<<dim3(gx, 1), 256>>>(Hh, W2t, cn2, cr2, Ph, Rh, n, 64);
    k_agg<64, false, false><<<(n + 7) / 8, 256>>>(Ph, Rh, g0, b0, m0, v0, out, n);
}